// round 15
// baseline (speedup 1.0000x reference)
#include <cuda_runtime.h>
#include <cstdint>

#define BB 256
#define TT 199
#define QQ 1000
#define NROW (BB * TT)               // 50,944
#define NEL  ((size_t)NROW * QQ)     // 50,944,000

// One packed accumulator per batch:
//   bits[63:56] arrival count (== TT when batch complete)
//   bits[55:48] masked-row count
//   bits[47:0]  bce sum, fixed-point * 2^20 (max ~2.1e13 < 2^48)
// Written only via fire-and-forget atomicAdd by worker blocks; consumed and
// reset (atomicExch) by the finalizer block. Fenceless: the packed word is
// simultaneously the data and the completion counter (same-address atomic
// serialization at the L2 atomic unit).
__device__ unsigned long long g_pack[BB];

// 1D grid of NROW+1 blocks. Blocks [0, NROW): proven hot-path body
// (117.5us, DRAM 82.1%). Block NROW: spin-finalizer (runs in the drain tail).
__global__ __launch_bounds__(256) void row_kernel(
    const float* __restrict__ pred,    // (B, T, Q)
    const float* __restrict__ batch,   // (B, T+1, Q)
    float* __restrict__ out)
{
    const int bid = blockIdx.x;
    const int tid = threadIdx.x;

    // ---------------- finalizer block ----------------
    if (bid == NROW) {
        const int b    = tid;
        const int lane = tid & 31;
        const int w    = tid >> 5;
        __shared__ double s_d[8];

        unsigned long long v = atomicAdd(&g_pack[b], 0ull);
        while ((v >> 56) != (unsigned long long)TT) {
            __nanosleep(300);
            v = atomicAdd(&g_pack[b], 0ull);
        }
        atomicExch(&g_pack[b], 0ull);   // reset for next graph replay

        const unsigned cnt = (unsigned)((v >> 48) & 0xFFull);
        const double  sum  = (double)(v & 0xFFFFFFFFFFFFull) * (1.0 / 1048576.0);
        double part = (cnt > 0) ? sum / ((double)cnt * (double)QQ) : 0.0;

        #pragma unroll
        for (int off = 16; off > 0; off >>= 1)
            part += __shfl_down_sync(0xFFFFFFFFu, part, off);
        if (lane == 0) s_d[w] = part;
        __syncthreads();
        if (tid < 8) {
            double x = s_d[tid];
            #pragma unroll
            for (int off = 4; off > 0; off >>= 1)
                x += __shfl_down_sync(0xFFu, x, off);
            if (tid == 0) out[0] = (float)x;
        }
        return;
    }

    // ---------------- worker blocks (proven body) ----------------
    const int t = bid % TT;
    const int b = bid / TT;
    const int lane = tid & 31;
    const int wid  = tid >> 5;

    const size_t row = (size_t)b * TT + t;
    const float* __restrict__ gt_row = batch + ((size_t)b * (TT + 1) + (t + 1)) * QQ;
    const float* __restrict__ p_row  = pred + row * QQ;

    __shared__ int   s_w[8];
    __shared__ float s_red[8];

    // ---- all 8 loads up front, unconditionally (max MLP) ----
    float g[4], p[4];
    #pragma unroll
    for (int k = 0; k < 4; k++) {
        int q = tid + 256 * k;
        bool valid = (k < 3) || (tid < QQ - 768);   // q < 1000
        g[k] = valid ? gt_row[q] : 0.0f;
        p[k] = valid ? p_row[q]  : 0.0f;
    }

    // ---- block-wide any(g == 1) ----
    int anyv = (g[0] == 1.0f) | (g[1] == 1.0f) | (g[2] == 1.0f) | (g[3] == 1.0f);
    unsigned wany = __ballot_sync(0xFFFFFFFFu, anyv);
    if (lane == 0) s_w[wid] = (wany != 0);
    __syncthreads();
    const int masked = s_w[0] | s_w[1] | s_w[2] | s_w[3] |
                       s_w[4] | s_w[5] | s_w[6] | s_w[7];
    const float fm = masked ? 1.0f : 0.0f;

    float* __restrict__ out_pred = out + 1 + row * QQ;
    float* __restrict__ out_gt   = out + 1 + NEL + row * QQ;

    float lsum = 0.0f;   // +(g*log p + (1-g)*log(1-p)); bce = -lsum
    #pragma unroll
    for (int k = 0; k < 4; k++) {
        int q = tid + 256 * k;
        bool valid = (k < 3) || (tid < QQ - 768);
        float pp = p[k], gg = g[k];
        float lp = fmaxf(__logf(pp),        -100.0f);
        float l1 = fmaxf(__logf(1.0f - pp), -100.0f);
        lsum += gg * lp + (1.0f - gg) * l1;
        if (valid) {
            out_pred[q] = pp * fm;
            out_gt[q]   = gg * fm;
        }
    }

    // ---- block reduction of lsum ----
    #pragma unroll
    for (int off = 16; off > 0; off >>= 1)
        lsum += __shfl_down_sync(0xFFFFFFFFu, lsum, off);
    if (lane == 0) s_red[wid] = lsum;
    __syncthreads();
    if (tid < 32) {
        float v = (tid < 8) ? s_red[tid] : 0.0f;
        #pragma unroll
        for (int off = 4; off > 0; off >>= 1)
            v += __shfl_down_sync(0xFFFFFFFFu, v, off);
        if (tid == 0) {
            out[1 + 2 * NEL + row] = fm;   // row_mask as float 0/1
            const double bce = (double)(fm * (-v));   // >= 0
            unsigned long long contrib =
                (1ull << 56)
                | (masked ? (1ull << 48) : 0ull)
                | (unsigned long long)(bce * 1048576.0 + 0.5);   // 2^20
            atomicAdd(&g_pack[b], contrib);   // fire-and-forget REDG
        }
    }
}

extern "C" void kernel_launch(void* const* d_in, const int* in_sizes, int n_in,
                              void* d_out, int out_size) {
    const float* pred  = (const float*)d_in[0];
    const float* batch = (const float*)d_in[1];
    float* out = (float*)d_out;

    row_kernel<<<NROW + 1, 256>>>(pred, batch, out);
}